// round 17
// baseline (speedup 1.0000x reference)
#include <cuda_runtime.h>
#include <cuda_bf16.h>
#include <cstdint>

// BS=32, SEQ_LEN=4096, HIDDEN=1024
// lengths ∈ [2048, 4096] ⇒ first zero of mask row (monotone 1..10..0) is at
// index ≥ 2048, so only mask[b, 2048:4096] needs scanning.
// n_valid = max(prefix-1, 1)
// bits[i] = fold(threefry2x32(key=(0,42), counter=(0,i)))  (JAX partitionable)
// u = bitcast((bits>>9)|0x3f800000)-1, clamped at 0
// idx = min(int(u*n_valid), n_valid-1); out[b,e] = tokens[b, idx, e]

static constexpr int BS = 32;
static constexpr int SEQ_LEN = 4096;
static constexpr int HIDDEN = 1024;
static constexpr int SCAN_BASE = SEQ_LEN / 2;   // 2048

// ---- JAX threefry2x32 (20 rounds), key = (0, 42) ----
__device__ __forceinline__ uint32_t rotl32(uint32_t x, int d) {
    return (x << d) | (x >> (32 - d));
}

__device__ __forceinline__ void threefry2x32(uint32_t k0, uint32_t k1,
                                             uint32_t& x0, uint32_t& x1) {
    const uint32_t ks2 = k0 ^ k1 ^ 0x1BD11BDAu;
    x0 += k0; x1 += k1;

#define TF_R4(a, b, c, d)                                        \
    x0 += x1; x1 = rotl32(x1, a); x1 ^= x0;                       \
    x0 += x1; x1 = rotl32(x1, b); x1 ^= x0;                       \
    x0 += x1; x1 = rotl32(x1, c); x1 ^= x0;                       \
    x0 += x1; x1 = rotl32(x1, d); x1 ^= x0;

    TF_R4(13, 15, 26, 6);   x0 += k1;  x1 += ks2 + 1u;
    TF_R4(17, 29, 16, 24);  x0 += ks2; x1 += k0  + 2u;
    TF_R4(13, 15, 26, 6);   x0 += k0;  x1 += k1  + 3u;
    TF_R4(17, 29, 16, 24);  x0 += k1;  x1 += ks2 + 4u;
    TF_R4(13, 15, 26, 6);   x0 += ks2; x1 += k0  + 5u;
#undef TF_R4
}

__global__ __launch_bounds__(1024, 1)
void condensed_embracement_kernel(const float* __restrict__ tokens,
                                  const int*   __restrict__ mask,
                                  float*       __restrict__ out) {
    const int b   = blockIdx.x;     // 0..31
    const int tid = threadIdx.x;    // 0..1023 (one per channel)
    const int wid = tid >> 5;       // 0..31
    const int lid = tid & 31;

    __shared__ int s_warpmin[32];

    // ---- mask load: only [2048, 4096), one int2 per thread, coalesced ----
    const int2* m2 = (const int2*)(mask + (size_t)b * SEQ_LEN + SCAN_BASE);
    int2 v = m2[tid];

    // ---- threefry while the load is in flight (independent ALU chain) ----
    const int n = b * HIDDEN + tid;
    uint32_t x0 = 0u, x1 = (uint32_t)n;
    threefry2x32(0u, 42u, x0, x1);
    const uint32_t bits = x0 ^ x1;
    float u = __uint_as_float((bits >> 9) | 0x3f800000u) - 1.0f;
    u = fmaxf(u, 0.0f);

    // ---- first-zero reduction: one barrier total ----
    int local_first = SEQ_LEN;
    if (v.y == 0) local_first = SCAN_BASE + 2 * tid + 1;
    if (v.x == 0) local_first = SCAN_BASE + 2 * tid + 0;

    int warp_min = __reduce_min_sync(0xFFFFFFFFu, local_first);
    if (lid == 0) s_warpmin[wid] = warp_min;
    __syncthreads();
    // every warp reduces the 32 warp minima (conflict-free LDS, no 2nd barrier)
    const int prefix = __reduce_min_sync(0xFFFFFFFFu, s_warpmin[lid]);

    const int n_valid = max(prefix - 1, 1);

    int idx = (int)(u * (float)n_valid);   // trunc toward zero == astype(int32)
    idx = min(idx, n_valid - 1);

    // ---- gather + coalesced store ----
    out[(size_t)b * HIDDEN + tid] =
        tokens[((size_t)b * SEQ_LEN + idx) * HIDDEN + tid];
}

extern "C" void kernel_launch(void* const* d_in, const int* in_sizes, int n_in,
                              void* d_out, int out_size) {
    // tokens: 32*4096*1024 elems, mask: 32*4096 elems
    const float* tokens;
    const int*   mask;
    if (n_in >= 2 && in_sizes[0] >= in_sizes[1]) {
        tokens = (const float*)d_in[0];
        mask   = (const int*)d_in[1];
    } else {
        tokens = (const float*)d_in[1];
        mask   = (const int*)d_in[0];
    }
    float* out = (float*)d_out;
    (void)out_size;

    condensed_embracement_kernel<<<BS, 1024>>>(tokens, mask, out);
}